// round 16
// baseline (speedup 1.0000x reference)
#include <cuda_runtime.h>

// ---------------------------------------------------------------------------
// RModel_29257317221019: fused cos-MLP deform (3->32->32->32->3) + trilinear
// sample from 256^3 volume.
// R15 base (2 pts/thread, f32x2 over output pairs, all weights __constant__
// as ulonglong2, __launch_bounds__(128,4)) with ACC-CARRIED layers:
// no h[32] arrays — each layer keeps pre-activation acc pairs and the next
// layer's k-loop applies __cosf inline right before use, dissolving the
// 64-wide MUFU bursts at layer boundaries into the FFMA2 stream.
// ---------------------------------------------------------------------------

typedef unsigned long long u64;

__device__ __forceinline__ void upk2(u64 v, float& lo, float& hi) {
    asm("mov.b64 {%0, %1}, %2;" : "=f"(lo), "=f"(hi) : "l"(v));
}
__device__ __forceinline__ u64 pk2(float lo, float hi) {
    u64 r; asm("mov.b64 %0, {%1, %2};" : "=l"(r) : "f"(lo), "f"(hi)); return r;
}
__device__ __forceinline__ u64 dup2(float v) {
    u64 r; asm("mov.b64 %0, {%1, %1};" : "=l"(r) : "f"(v)); return r;
}
__device__ __forceinline__ u64 ffma2(u64 a, u64 b, u64 c) {
    u64 r; asm("fma.rn.f32x2 %0, %1, %2, %3;" : "=l"(r) : "l"(a), "l"(b), "l"(c)); return r;
}

// Constant weights, natively ulonglong2 (immediate-offset LDC.128):
__constant__ ulonglong2 cW1[3][8];
__constant__ ulonglong2 cB1[8];
__constant__ ulonglong2 cW2[32][8];
__constant__ ulonglong2 cB2[8];
__constant__ ulonglong2 cW3[32][8];
__constant__ ulonglong2 cB3[8];
// Final layer, prepacked by prep_kernel:
//   cWfP[k]  = ((Wf[k][0],Wf[k][1]), (Wf[k][2],0)),  k = 0..31
//   cWfP[32] = ((bf0,bf1), (bf2,0))
__constant__ ulonglong2 cWfP[33];

__device__ u64 g_wf_scratch[66];

__global__ void prep_kernel(const float* __restrict__ Wf,
                            const float* __restrict__ bf) {
    int k = threadIdx.x;
    if (k < 32) {
        g_wf_scratch[2 * k]     = pk2(Wf[3 * k + 0], Wf[3 * k + 1]);
        g_wf_scratch[2 * k + 1] = pk2(Wf[3 * k + 2], 0.0f);
    }
    if (k == 0) {
        g_wf_scratch[64] = pk2(bf[0], bf[1]);
        g_wf_scratch[65] = pk2(bf[2], 0.0f);
    }
}

#define BLK 128

__global__ __launch_bounds__(BLK, 4)
void deform_sample_kernel(
    const float* __restrict__ x,
    const float* __restrict__ vol,
    float* __restrict__ out,
    int npairs)
{
    int t = blockIdx.x * blockDim.x + threadIdx.x;
    if (t >= npairs) return;

    // Two consecutive points (x layout: 4 floats/point, coords in [0:3])
    const float4* x4 = reinterpret_cast<const float4*>(x);
    float4 XA = x4[2 * t + 0];
    float4 XB = x4[2 * t + 1];

    // Two acc banks per point; roles alternate between "previous layer's
    // pre-activations" and "current layer's accumulators".
    u64 pA[16], pB[16];    // prev-layer accs (pre-activation pairs)
    u64 aA[16], aB[16];    // current-layer accs

    // ---- Layer 1: pre-activations only (no cos yet) ----
    {
        u64 cA0 = dup2(XA.x), cA1 = dup2(XA.y), cA2 = dup2(XA.z);
        u64 cB0 = dup2(XB.x), cB1v = dup2(XB.y), cB2v = dup2(XB.z);
#pragma unroll
        for (int q = 0; q < 8; q++) {           // d = 4q .. 4q+3
            ulonglong2 bb = cB1[q];
            u64 qA0 = bb.x, qA1 = bb.y, qB0 = bb.x, qB1 = bb.y;
            ulonglong2 w0 = cW1[0][q];
            ulonglong2 w1 = cW1[1][q];
            ulonglong2 w2 = cW1[2][q];
            qA0 = ffma2(cA0, w0.x, qA0);  qA1 = ffma2(cA0, w0.y, qA1);
            qB0 = ffma2(cB0, w0.x, qB0);  qB1 = ffma2(cB0, w0.y, qB1);
            qA0 = ffma2(cA1, w1.x, qA0);  qA1 = ffma2(cA1, w1.y, qA1);
            qB0 = ffma2(cB1v, w1.x, qB0); qB1 = ffma2(cB1v, w1.y, qB1);
            qA0 = ffma2(cA2, w2.x, qA0);  qA1 = ffma2(cA2, w2.y, qA1);
            qB0 = ffma2(cB2v, w2.x, qB0); qB1 = ffma2(cB2v, w2.y, qB1);
            pA[2*q] = qA0; pA[2*q+1] = qA1;
            pB[2*q] = qB0; pB[2*q+1] = qB1;
        }
    }

    // ---- Layer 2: aA/aB = acc(cos(pA/pB) @ W2 + b2), cos inline ----
#pragma unroll
    for (int m = 0; m < 8; m++) {
        ulonglong2 b = cB2[m];
        aA[2*m] = b.x; aA[2*m+1] = b.y;
        aB[2*m] = b.x; aB[2*m+1] = b.y;
    }
#pragma unroll
    for (int kk = 0; kk < 16; kk++) {           // k = 2kk, 2kk+1
        float a0, a1, b0, b1;
        upk2(pA[kk], a0, a1);
        upk2(pB[kk], b0, b1);
        u64 dA0 = dup2(__cosf(a0));
        u64 dB0 = dup2(__cosf(b0));
#pragma unroll
        for (int m = 0; m < 8; m++) {
            ulonglong2 w = cW2[2*kk][m];
            aA[2*m]   = ffma2(dA0, w.x, aA[2*m]);
            aA[2*m+1] = ffma2(dA0, w.y, aA[2*m+1]);
            aB[2*m]   = ffma2(dB0, w.x, aB[2*m]);
            aB[2*m+1] = ffma2(dB0, w.y, aB[2*m+1]);
        }
        u64 dA1 = dup2(__cosf(a1));
        u64 dB1 = dup2(__cosf(b1));
#pragma unroll
        for (int m = 0; m < 8; m++) {
            ulonglong2 w = cW2[2*kk+1][m];
            aA[2*m]   = ffma2(dA1, w.x, aA[2*m]);
            aA[2*m+1] = ffma2(dA1, w.y, aA[2*m+1]);
            aB[2*m]   = ffma2(dB1, w.x, aB[2*m]);
            aB[2*m+1] = ffma2(dB1, w.y, aB[2*m+1]);
        }
    }

    // ---- Layer 3: pA/pB = acc(cos(aA/aB) @ W3 + b3), cos inline ----
#pragma unroll
    for (int m = 0; m < 8; m++) {
        ulonglong2 b = cB3[m];
        pA[2*m] = b.x; pA[2*m+1] = b.y;
        pB[2*m] = b.x; pB[2*m+1] = b.y;
    }
#pragma unroll
    for (int kk = 0; kk < 16; kk++) {
        float a0, a1, b0, b1;
        upk2(aA[kk], a0, a1);
        upk2(aB[kk], b0, b1);
        u64 dA0 = dup2(__cosf(a0));
        u64 dB0 = dup2(__cosf(b0));
#pragma unroll
        for (int m = 0; m < 8; m++) {
            ulonglong2 w = cW3[2*kk][m];
            pA[2*m]   = ffma2(dA0, w.x, pA[2*m]);
            pA[2*m+1] = ffma2(dA0, w.y, pA[2*m+1]);
            pB[2*m]   = ffma2(dB0, w.x, pB[2*m]);
            pB[2*m+1] = ffma2(dB0, w.y, pB[2*m+1]);
        }
        u64 dA1 = dup2(__cosf(a1));
        u64 dB1 = dup2(__cosf(b1));
#pragma unroll
        for (int m = 0; m < 8; m++) {
            ulonglong2 w = cW3[2*kk+1][m];
            pA[2*m]   = ffma2(dA1, w.x, pA[2*m]);
            pA[2*m+1] = ffma2(dA1, w.y, pA[2*m+1]);
            pB[2*m]   = ffma2(dB1, w.x, pB[2*m]);
            pB[2*m+1] = ffma2(dB1, w.y, pB[2*m+1]);
        }
    }

    // ---- Final: coord = c + 5 * (cos(pA/pB) @ Wf + bf), cos inline ----
    float pxy[2][3];
    {
        ulonglong2 bb = cWfP[32];
        u64 eA01 = bb.x, eA2 = bb.y;
        u64 eB01 = bb.x, eB2 = bb.y;
#pragma unroll
        for (int kk = 0; kk < 16; kk++) {       // k = 2kk, 2kk+1
            float a0, a1, b0, b1;
            upk2(pA[kk], a0, a1);
            upk2(pB[kk], b0, b1);
            u64 dA0 = dup2(__cosf(a0));
            u64 dB0 = dup2(__cosf(b0));
            ulonglong2 w = cWfP[2*kk];          // (w01, w2x)
            eA01 = ffma2(dA0, w.x, eA01);
            eA2  = ffma2(dA0, w.y, eA2);
            eB01 = ffma2(dB0, w.x, eB01);
            eB2  = ffma2(dB0, w.y, eB2);
            u64 dA1 = dup2(__cosf(a1));
            u64 dB1 = dup2(__cosf(b1));
            ulonglong2 w1 = cWfP[2*kk+1];
            eA01 = ffma2(dA1, w1.x, eA01);
            eA2  = ffma2(dA1, w1.y, eA2);
            eB01 = ffma2(dB1, w1.x, eB01);
            eB2  = ffma2(dB1, w1.y, eB2);
        }
        float f0, f1, f2, jk;
        upk2(eA01, f0, f1); upk2(eA2, f2, jk);
        pxy[0][0] = fmaf(5.0f, f0, XA.x);
        pxy[0][1] = fmaf(5.0f, f1, XA.y);
        pxy[0][2] = fmaf(5.0f, f2, XA.z);
        upk2(eB01, f0, f1); upk2(eB2, f2, jk);
        pxy[1][0] = fmaf(5.0f, f0, XB.x);
        pxy[1][1] = fmaf(5.0f, f1, XB.y);
        pxy[1][2] = fmaf(5.0f, f2, XB.z);
    }

    // ---- Trilinear sample (scalar per point) ----
    float res[2];
#pragma unroll
    for (int s = 0; s < 2; s++) {
        float cx = fminf(fmaxf(pxy[s][0], 0.0f), 255.0f);
        float cy = fminf(fmaxf(pxy[s][1], 0.0f), 255.0f);
        float cz = fminf(fmaxf(pxy[s][2], 0.0f), 255.0f);

        float fx0 = floorf(cx), fy0 = floorf(cy), fz0 = floorf(cz);
        int ix0 = (int)fx0, iy0 = (int)fy0, iz0 = (int)fz0;
        int ix1 = min(ix0 + 1, 255);
        int iy1 = min(iy0 + 1, 255);
        int iz1 = min(iz0 + 1, 255);

        float fx = cx - fx0, fy = cy - fy0, fz = cz - fz0;
        float gx = 1.0f - fx, gy = 1.0f - fy, gz = 1.0f - fz;

        int X0 = ix0 << 16, X1 = ix1 << 16;
        int Y0 = iy0 << 8,  Y1 = iy1 << 8;

        float v000 = __ldg(vol + (X0 + Y0 + iz0));
        float v100 = __ldg(vol + (X1 + Y0 + iz0));
        float v010 = __ldg(vol + (X0 + Y1 + iz0));
        float v001 = __ldg(vol + (X0 + Y0 + iz1));
        float v110 = __ldg(vol + (X1 + Y1 + iz0));
        float v101 = __ldg(vol + (X1 + Y0 + iz1));
        float v011 = __ldg(vol + (X0 + Y1 + iz1));
        float v111 = __ldg(vol + (X1 + Y1 + iz1));

        float r;
        r  = v000 * (gx * gy * gz);
        r += v100 * (fx * gy * gz);
        r += v010 * (gx * fy * gz);
        r += v001 * (gx * gy * fz);
        r += v110 * (fx * fy * gz);
        r += v101 * (fx * gy * fz);
        r += v011 * (gx * fy * fz);
        r += v111 * (fx * fy * fz);
        res[s] = r;
    }

    float2 o; o.x = res[0]; o.y = res[1];
    reinterpret_cast<float2*>(out)[t] = o;
}

extern "C" void kernel_launch(void* const* d_in, const int* in_sizes, int n_in,
                              void* d_out, int out_size) {
    const float* x   = (const float*)d_in[0];
    const float* vol = (const float*)d_in[9];
    float* out = (float*)d_out;

    // Stage weights into constant memory (D2D memcpy nodes; capturable).
    cudaMemcpyToSymbolAsync(cW1, d_in[1], 3  * 32 * 4, 0, cudaMemcpyDeviceToDevice, 0);
    cudaMemcpyToSymbolAsync(cB1, d_in[2], 32 * 4,      0, cudaMemcpyDeviceToDevice, 0);
    cudaMemcpyToSymbolAsync(cW2, d_in[3], 32 * 32 * 4, 0, cudaMemcpyDeviceToDevice, 0);
    cudaMemcpyToSymbolAsync(cB2, d_in[4], 32 * 4,      0, cudaMemcpyDeviceToDevice, 0);
    cudaMemcpyToSymbolAsync(cW3, d_in[5], 32 * 32 * 4, 0, cudaMemcpyDeviceToDevice, 0);
    cudaMemcpyToSymbolAsync(cB3, d_in[6], 32 * 4,      0, cudaMemcpyDeviceToDevice, 0);

    // Prepack final-layer pairs on device, then stage into constant memory.
    prep_kernel<<<1, 32>>>((const float*)d_in[7], (const float*)d_in[8]);
    void* sp = 0;
    cudaGetSymbolAddress(&sp, g_wf_scratch);
    cudaMemcpyToSymbolAsync(cWfP, sp, 66 * 8, 0, cudaMemcpyDeviceToDevice, 0);

    int npts = out_size;           // 2,097,152 points
    int npairs = npts / 2;         // 2 points per thread
    int grid = (npairs + BLK - 1) / BLK;

    deform_sample_kernel<<<grid, BLK>>>(x, vol, out, npairs);
}